// round 2
// baseline (speedup 1.0000x reference)
#include <cuda_runtime.h>
#include <cuda_bf16.h>

#define NUSERS 100000
#define NITEMS 50000
#define DIM 64
#define NNODES 150001            // users + items + padding row
#define ND 9600064               // NNODES * DIM
#define NEDGES 4800000

// Index stride: 2 if indices arrive as int64 (read low words), 1 if int32.
__device__ int g_idx_stride;

// ---------------------------------------------------------------------------
// Detector: for int64 little-endian indices with values < 2^31, every odd
// 32-bit word is zero. For int32 indices those words are random node ids.
// Checking 32 of them makes a false positive ~impossible ((1/150001)^32).
// Runs every replay (deterministic, same result each time).
// ---------------------------------------------------------------------------
__global__ void gcn_detect_kernel(const int* __restrict__ rows32,
                                  const int* __restrict__ cols32) {
    bool is64 = true;
    #pragma unroll
    for (int k = 0; k < 16; k++) {
        if (rows32[2 * k + 1] != 0) is64 = false;
        if (cols32[2 * k + 1] != 0) is64 = false;
    }
    g_idx_stride = is64 ? 2 : 1;
}

// ---------------------------------------------------------------------------
// Kernel 1: ego = concat(user_emb, item_emb); zero h1..h3 (atomics accumulate,
// so zeroing must happen every replay). float4 vectorized.
// ---------------------------------------------------------------------------
__global__ void gcn_init_kernel(const float4* __restrict__ user_emb,
                                const float4* __restrict__ item_emb,
                                float4* __restrict__ ego,
                                float4* __restrict__ h1,
                                float4* __restrict__ h2,
                                float4* __restrict__ h3) {
    const int n4 = ND / 4;
    const int u4 = NUSERS * (DIM / 4);
    int i = blockIdx.x * blockDim.x + threadIdx.x;
    if (i < n4) {
        float4 v = (i < u4) ? user_emb[i] : item_emb[i - u4];
        ego[i] = v;
        float4 z = make_float4(0.f, 0.f, 0.f, 0.f);
        h1[i] = z;
        h2[i] = z;
        h3[i] = z;
    }
}

// ---------------------------------------------------------------------------
// Kernel 2: COO SpMM scatter.  y[r] += v * h[c]  per edge.
// 16 threads per edge, one float4 each. Scatter via red.global.add.v4.f32:
// one L2-side reduction per 16B, no return path.
// ---------------------------------------------------------------------------
__global__ void gcn_spmm_kernel(const int* __restrict__ rowsw,
                                const int* __restrict__ colsw,
                                const float* __restrict__ vals,
                                const float* __restrict__ h,
                                float* __restrict__ y) {
    int t = blockIdx.x * blockDim.x + threadIdx.x;
    int e = t >> 4;
    if (e >= NEDGES) return;
    int sub = t & 15;
    int stride = g_idx_stride;

    int r = rowsw[e * stride];
    int c = colsw[e * stride];
    float v = vals[e];

    const float4* __restrict__ hrow =
        reinterpret_cast<const float4*>(h + (long long)c * DIM);
    float4 hv = hrow[sub];
    hv.x *= v; hv.y *= v; hv.z *= v; hv.w *= v;

    float* dst = y + (long long)r * DIM + sub * 4;
    asm volatile("red.global.add.v4.f32 [%0], {%1, %2, %3, %4};"
                 :: "l"(dst), "f"(hv.x), "f"(hv.y), "f"(hv.z), "f"(hv.w)
                 : "memory");
}

// ---------------------------------------------------------------------------
// Kernel 3: h_sum = ego + h1 + h2 + h3.
// ---------------------------------------------------------------------------
__global__ void gcn_sum_kernel(const float4* __restrict__ ego,
                               const float4* __restrict__ h1,
                               const float4* __restrict__ h2,
                               const float4* __restrict__ h3,
                               float4* __restrict__ hsum) {
    const int n4 = ND / 4;
    int i = blockIdx.x * blockDim.x + threadIdx.x;
    if (i < n4) {
        float4 a = ego[i], b = h1[i], c = h2[i], d = h3[i];
        float4 s;
        s.x = a.x + b.x + c.x + d.x;
        s.y = a.y + b.y + c.y + d.y;
        s.z = a.z + b.z + c.z + d.z;
        s.w = a.w + b.w + c.w + d.w;
        hsum[i] = s;
    }
}

// ---------------------------------------------------------------------------
// kernel_launch — graph-capturable, allocation-free.
// Output layout (out_size = 5*ND): [h_sum | ego | h1 | h2 | h3]
// ---------------------------------------------------------------------------
extern "C" void kernel_launch(void* const* d_in, const int* in_sizes, int n_in,
                              void* d_out, int out_size) {
    const float* user_emb = (const float*)d_in[0];   // [100000, 64] f32
    const float* item_emb = (const float*)d_in[1];   // [50001, 64] f32
    const float* vals     = (const float*)d_in[2];   // [4.8M] f32
    const int*   rowsw    = (const int*)d_in[3];     // int32 or int64 words
    const int*   colsw    = (const int*)d_in[4];

    float* out  = (float*)d_out;
    float* hsum = out;
    float* ego  = out + (size_t)ND;
    float* h1   = out + (size_t)2 * ND;
    float* h2   = out + (size_t)3 * ND;
    float* h3   = out + (size_t)4 * ND;

    gcn_detect_kernel<<<1, 1>>>(rowsw, colsw);

    const int n4 = ND / 4;
    {
        dim3 blk(256), grd((n4 + 255) / 256);
        gcn_init_kernel<<<grd, blk>>>((const float4*)user_emb,
                                      (const float4*)item_emb,
                                      (float4*)ego, (float4*)h1,
                                      (float4*)h2, (float4*)h3);
    }

    {
        long long total = (long long)NEDGES * 16;   // 16 threads per edge
        dim3 blk(256), grd((unsigned)((total + 255) / 256));
        gcn_spmm_kernel<<<grd, blk>>>(rowsw, colsw, vals, ego, h1);
        gcn_spmm_kernel<<<grd, blk>>>(rowsw, colsw, vals, h1, h2);
        gcn_spmm_kernel<<<grd, blk>>>(rowsw, colsw, vals, h2, h3);
    }

    {
        dim3 blk(256), grd((n4 + 255) / 256);
        gcn_sum_kernel<<<grd, blk>>>((const float4*)ego, (const float4*)h1,
                                     (const float4*)h2, (const float4*)h3,
                                     (float4*)hsum);
    }
}

// round 3
// speedup vs baseline: 1.9366x; 1.9366x over previous
#include <cuda_runtime.h>
#include <cuda_bf16.h>

#define NUSERS 100000
#define NITEMS 50000
#define DIM 64
#define NNODES 150001            // users + items + padding row
#define ND 9600064               // NNODES * DIM
#define NEDGES 4800000

#define SCAN_CHUNK 512
#define NB_SCAN ((NNODES + SCAN_CHUNK - 1) / SCAN_CHUNK)   // 293

// ---------------- device scratch (static allocation — allowed) -------------
__device__ int   g_idx_stride;            // 2 if int64 indices, 1 if int32
__device__ int   g_counts[NNODES];
__device__ int   g_rowptr[NNODES + 1];
__device__ int   g_cursor[NNODES];
__device__ int   g_blocksums[SCAN_CHUNK]; // >= NB_SCAN
__device__ int2  g_edges[NEDGES];         // .x = col, .y = float bits of val

// ---------------------------------------------------------------------------
// Detect index width: int64 little-endian values < 2^31 have zero high words.
// ---------------------------------------------------------------------------
__global__ void gcn_detect_kernel(const int* __restrict__ rows32,
                                  const int* __restrict__ cols32) {
    bool is64 = true;
    #pragma unroll
    for (int k = 0; k < 16; k++) {
        if (rows32[2 * k + 1] != 0) is64 = false;
        if (cols32[2 * k + 1] != 0) is64 = false;
    }
    g_idx_stride = is64 ? 2 : 1;
}

// ---------------------------------------------------------------------------
// Zero the degree counters (needed every replay).
// ---------------------------------------------------------------------------
__global__ void gcn_zero_counts(void) {
    int i = blockIdx.x * blockDim.x + threadIdx.x;
    if (i < NNODES) g_counts[i] = 0;
}

// ---------------------------------------------------------------------------
// Histogram of row degrees.
// ---------------------------------------------------------------------------
__global__ void gcn_hist_kernel(const int* __restrict__ rowsw) {
    int e = blockIdx.x * blockDim.x + threadIdx.x;
    if (e < NEDGES) {
        int r = rowsw[e * g_idx_stride];
        atomicAdd(&g_counts[r], 1);      // compiles to RED (no return use)
    }
}

// ---------------------------------------------------------------------------
// Exclusive scan, 3 phases. Phase 1: per-block sums.
// ---------------------------------------------------------------------------
__global__ void gcn_scan1(void) {
    __shared__ int s[SCAN_CHUNK];
    int t = threadIdx.x;
    int i = blockIdx.x * SCAN_CHUNK + t;
    s[t] = (i < NNODES) ? g_counts[i] : 0;
    __syncthreads();
    for (int off = SCAN_CHUNK / 2; off > 0; off >>= 1) {
        if (t < off) s[t] += s[t + off];
        __syncthreads();
    }
    if (t == 0) g_blocksums[blockIdx.x] = s[0];
}

// Phase 2: single-block exclusive scan of block sums.
__global__ void gcn_scan2(void) {
    __shared__ int s[SCAN_CHUNK];
    int t = threadIdx.x;
    int x = (t < NB_SCAN) ? g_blocksums[t] : 0;
    s[t] = x;
    __syncthreads();
    for (int off = 1; off < SCAN_CHUNK; off <<= 1) {
        int v = (t >= off) ? s[t - off] : 0;
        __syncthreads();
        s[t] += v;
        __syncthreads();
    }
    if (t < NB_SCAN) g_blocksums[t] = s[t] - x;   // exclusive
}

// Phase 3: scan within block + offset; write rowptr & cursor.
__global__ void gcn_scan3(void) {
    __shared__ int s[SCAN_CHUNK];
    int t = threadIdx.x;
    int i = blockIdx.x * SCAN_CHUNK + t;
    int x = (i < NNODES) ? g_counts[i] : 0;
    s[t] = x;
    __syncthreads();
    for (int off = 1; off < SCAN_CHUNK; off <<= 1) {
        int v = (t >= off) ? s[t - off] : 0;
        __syncthreads();
        s[t] += v;
        __syncthreads();
    }
    if (i < NNODES) {
        int excl = g_blocksums[blockIdx.x] + s[t] - x;
        g_rowptr[i] = excl;
        g_cursor[i] = excl;
    }
    if (i == 0) g_rowptr[NNODES] = NEDGES;
}

// ---------------------------------------------------------------------------
// Scatter edges into CSR slots (packed col+val).
// ---------------------------------------------------------------------------
__global__ void gcn_scatter_kernel(const int* __restrict__ rowsw,
                                   const int* __restrict__ colsw,
                                   const float* __restrict__ vals) {
    int e = blockIdx.x * blockDim.x + threadIdx.x;
    if (e < NEDGES) {
        int stride = g_idx_stride;
        int r = rowsw[e * stride];
        int c = colsw[e * stride];
        float v = vals[e];
        int pos = atomicAdd(&g_cursor[r], 1);
        g_edges[pos] = make_int2(c, __float_as_int(v));
    }
}

// ---------------------------------------------------------------------------
// ego = concat(user_emb, item_emb). Other layers are fully overwritten by
// the CSR spmm (every node written), so no zeroing needed.
// ---------------------------------------------------------------------------
__global__ void gcn_init_kernel(const float4* __restrict__ user_emb,
                                const float4* __restrict__ item_emb,
                                float4* __restrict__ ego) {
    const int n4 = ND / 4;
    const int u4 = NUSERS * (DIM / 4);
    int i = blockIdx.x * blockDim.x + threadIdx.x;
    if (i < n4)
        ego[i] = (i < u4) ? user_emb[i] : item_emb[i - u4];
}

// ---------------------------------------------------------------------------
// CSR SpMM: one warp per node, float2 per lane (32 x 2 = 64 dims).
// 2-way unrolled gather loop (MLP). Optional fused epilogue computes
// hsum = ego + h1 + h2 + h3 on the last layer.
// ---------------------------------------------------------------------------
template <bool FUSE>
__global__ void gcn_csr_spmm(const float* __restrict__ h,
                             float* __restrict__ y,
                             const float* __restrict__ ego,
                             const float* __restrict__ h1,
                             const float* __restrict__ h2,
                             float* __restrict__ hsum) {
    int warp = (blockIdx.x * blockDim.x + threadIdx.x) >> 5;
    if (warp >= NNODES) return;
    int lane = threadIdx.x & 31;
    int off = lane * 2;

    int start = g_rowptr[warp];
    int end   = g_rowptr[warp + 1];

    float ax = 0.f, ay = 0.f;
    int i = start;
    for (; i + 1 < end; i += 2) {
        int2 e0 = g_edges[i];
        int2 e1 = g_edges[i + 1];
        const float2 p0 = *reinterpret_cast<const float2*>(
            h + (size_t)e0.x * DIM + off);
        const float2 p1 = *reinterpret_cast<const float2*>(
            h + (size_t)e1.x * DIM + off);
        float v0 = __int_as_float(e0.y);
        float v1 = __int_as_float(e1.y);
        ax += v0 * p0.x + v1 * p1.x;
        ay += v0 * p0.y + v1 * p1.y;
    }
    if (i < end) {
        int2 e0 = g_edges[i];
        const float2 p0 = *reinterpret_cast<const float2*>(
            h + (size_t)e0.x * DIM + off);
        float v0 = __int_as_float(e0.y);
        ax += v0 * p0.x;
        ay += v0 * p0.y;
    }

    size_t base = (size_t)warp * DIM + off;
    *reinterpret_cast<float2*>(y + base) = make_float2(ax, ay);

    if (FUSE) {
        float2 a = *reinterpret_cast<const float2*>(ego + base);
        float2 b = *reinterpret_cast<const float2*>(h1 + base);
        float2 c = *reinterpret_cast<const float2*>(h2 + base);
        *reinterpret_cast<float2*>(hsum + base) =
            make_float2(a.x + b.x + c.x + ax, a.y + b.y + c.y + ay);
    }
}

// ---------------------------------------------------------------------------
// kernel_launch — graph-capturable, allocation-free.
// Output layout (out_size = 5*ND): [h_sum | ego | h1 | h2 | h3]
// ---------------------------------------------------------------------------
extern "C" void kernel_launch(void* const* d_in, const int* in_sizes, int n_in,
                              void* d_out, int out_size) {
    const float* user_emb = (const float*)d_in[0];
    const float* item_emb = (const float*)d_in[1];
    const float* vals     = (const float*)d_in[2];
    const int*   rowsw    = (const int*)d_in[3];
    const int*   colsw    = (const int*)d_in[4];

    float* out  = (float*)d_out;
    float* hsum = out;
    float* ego  = out + (size_t)ND;
    float* h1   = out + (size_t)2 * ND;
    float* h2   = out + (size_t)3 * ND;
    float* h3   = out + (size_t)4 * ND;

    gcn_detect_kernel<<<1, 1>>>(rowsw, colsw);

    // --- CSR build ---
    gcn_zero_counts<<<(NNODES + 255) / 256, 256>>>();
    gcn_hist_kernel<<<(NEDGES + 255) / 256, 256>>>(rowsw);
    gcn_scan1<<<NB_SCAN, SCAN_CHUNK>>>();
    gcn_scan2<<<1, SCAN_CHUNK>>>();
    gcn_scan3<<<NB_SCAN, SCAN_CHUNK>>>();
    gcn_scatter_kernel<<<(NEDGES + 255) / 256, 256>>>(rowsw, colsw, vals);

    // --- ego copy (runs concurrently-ish on same stream; order irrelevant
    //     until spmm1, which needs both ego and CSR) ---
    {
        const int n4 = ND / 4;
        gcn_init_kernel<<<(n4 + 255) / 256, 256>>>(
            (const float4*)user_emb, (const float4*)item_emb, (float4*)ego);
    }

    // --- 3 propagation layers (warp per node) ---
    {
        long long threads = (long long)NNODES * 32;
        unsigned grd = (unsigned)((threads + 255) / 256);
        gcn_csr_spmm<false><<<grd, 256>>>(ego, h1, nullptr, nullptr, nullptr,
                                          nullptr);
        gcn_csr_spmm<false><<<grd, 256>>>(h1, h2, nullptr, nullptr, nullptr,
                                          nullptr);
        gcn_csr_spmm<true><<<grd, 256>>>(h2, h3, ego, h1, h2, hsum);
    }
}